// round 6
// baseline (speedup 1.0000x reference)
#include <cuda_runtime.h>

#define F_DIM 256
#define NB 32
#define P_DIM 32
#define THREADS 768
#define NWARPS (THREADS / 32)

// Cross-block accumulators. Zero at process start; the LAST block of every
// launch resets them after consuming, so graph replays are deterministic.
__device__ int g_hist[64];
__device__ unsigned int g_ctr = 0;

// Fast bin: bins verified on-device to be exactly k/32 (exact in fp32, so
// floor(x*32) clipped == count(x >= k/32) - 1 clipped). NaN->0 via F2I, and
// both paths clamp to [0,31], so all gather addresses stay in-bounds.
__device__ __forceinline__ int bin_uni(float v) {
    int k = (int)(v * 32.0f);
    k = k < 0 ? 0 : k;
    return k > 31 ? 31 : k;
}
// Generic fallback: exact reference semantics, edges read from gmem.
__device__ __forceinline__ int bin_gen(float v, const float* __restrict__ e) {
    int c = 0;
#pragma unroll
    for (int k = 0; k < 33; ++k) c += (v >= e[k]) ? 1 : 0;
    c -= 1;
    c = c < 0 ? 0 : c;
    return c > 31 ? 31 : c;
}

// ---------------- fast path: uniform bins + pairs (2p, 2p+1) ----------------
// Two rows per iteration, manually interleaved; next pair prefetched.
__device__ void fast_loop(const float* __restrict__ x, float* __restrict__ out,
                          const float* __restrict__ sW, const float* __restrict__ sIW,
                          int* __restrict__ sHist,
                          int lane, int gw, int nw, int B, float icpt)
{
    int h0 = 0, h5 = 0;
    const float4* xp = (const float4*)x;
    const int fa = 4 * lane;
    const int fc = 128 + 4 * lane;
    const unsigned full = 0xffffffffu;

    int r = gw;
    if (r < B) {
        const int step = 2 * nw;
        bool v1 = (r + nw) < B;
        int r1 = v1 ? r + nw : r;            // clamped: loads stay valid
        float4 a0, c0, a1, c1;
        {
            size_t b0 = (size_t)r * 64, b1 = (size_t)r1 * 64;
            a0 = xp[b0 + lane];      c0 = xp[b0 + 32 + lane];
            a1 = xp[b1 + lane];      c1 = xp[b1 + 32 + lane];
        }

        while (true) {
            // ---- prefetch next row pair (clamped, branchless) ----
            int rn = r + step;
            bool nv0 = rn < B;
            int rn0 = nv0 ? rn : (B - 1);
            bool nv1 = (rn + nw) < B;
            int rn1 = nv1 ? rn + nw : rn0;
            float4 na0, nc0, na1, nc1;
            {
                size_t b0 = (size_t)rn0 * 64, b1 = (size_t)rn1 * 64;
                na0 = xp[b0 + lane];     nc0 = xp[b0 + 32 + lane];
                na1 = xp[b1 + lane];     nc1 = xp[b1 + 32 + lane];
            }

            // ---- bins for both rows (pure register math) ----
            int p0 = bin_uni(a0.x), p1 = bin_uni(a0.y), p2 = bin_uni(a0.z), p3 = bin_uni(a0.w);
            int p4 = bin_uni(c0.x), p5 = bin_uni(c0.y), p6 = bin_uni(c0.z), p7 = bin_uni(c0.w);
            int q0 = bin_uni(a1.x), q1 = bin_uni(a1.y), q2 = bin_uni(a1.z), q3 = bin_uni(a1.w);
            int q4 = bin_uni(c1.x), q5 = bin_uni(c1.y), q6 = bin_uni(c1.z), q7 = bin_uni(c1.w);

            // ---- W gathers (stride-33 padded), both rows interleaved ----
            float s0 = sW[(fa + 0) * 33 + p0] + sW[(fa + 1) * 33 + p1]
                     + sW[(fa + 2) * 33 + p2] + sW[(fa + 3) * 33 + p3]
                     + sW[(fc + 0) * 33 + p4] + sW[(fc + 1) * 33 + p5]
                     + sW[(fc + 2) * 33 + p6] + sW[(fc + 3) * 33 + p7];
            float s1 = sW[(fa + 0) * 33 + q0] + sW[(fa + 1) * 33 + q1]
                     + sW[(fa + 2) * 33 + q2] + sW[(fa + 3) * 33 + q3]
                     + sW[(fc + 0) * 33 + q4] + sW[(fc + 1) * 33 + q5]
                     + sW[(fc + 2) * 33 + q6] + sW[(fc + 3) * 33 + q7];

            // ---- interaction: pair p = features (2p, 2p+1); one shfl/row ----
            unsigned w0 = (unsigned)p0 | ((unsigned)p1 << 8) | ((unsigned)p2 << 16) | ((unsigned)p3 << 24);
            unsigned w1 = (unsigned)q0 | ((unsigned)q1 << 8) | ((unsigned)q2 << 16) | ((unsigned)q3 << 24);
            unsigned e0 = __shfl_sync(full, w0, lane >> 1);
            unsigned e1 = __shfl_sync(full, w1, lane >> 1);
            int sh = (lane & 1) << 4;
            s0 += sIW[lane * 1024 + ((e0 >> sh) & 0xff) * 32 + ((e0 >> (sh + 8)) & 0xff)];
            s1 += sIW[lane * 1024 + ((e1 >> sh) & 0xff) * 32 + ((e1 >> (sh + 8)) & 0xff)];

            // ---- sensitive histograms via register counters (no atomics) ----
            int b0a = __shfl_sync(full, p0, 0);   // feature 0 = lane0 .x
            int b5a = __shfl_sync(full, p1, 1);   // feature 5 = lane1 .y
            int b0b = __shfl_sync(full, q0, 0);
            int b5b = __shfl_sync(full, q1, 1);
            h0 += (lane == b0a);
            h5 += (lane == b5a);
            if (v1) { h0 += (lane == b0b); h5 += (lane == b5b); }

            // ---- dual butterfly reduce (independent chains pipeline) ----
#pragma unroll
            for (int off = 16; off > 0; off >>= 1) {
                s0 += __shfl_xor_sync(full, s0, off);
                s1 += __shfl_xor_sync(full, s1, off);
            }
            if (lane == 0) {
                out[r] = icpt + s0;
                if (v1) out[r + nw] = icpt + s1;
            }

            if (!nv0) break;
            r = rn; v1 = nv1;
            a0 = na0; c0 = nc0; a1 = na1; c1 = nc1;
        }
    }
    // one flush per warp
    atomicAdd(&sHist[lane], h0);
    atomicAdd(&sHist[32 + lane], h5);
}

// ---------------- generic fallback (correctness only) ----------------
__device__ void slow_loop(const float* __restrict__ x, float* __restrict__ out,
                          const float* __restrict__ sW, const float* __restrict__ sIW,
                          const float* __restrict__ bins,
                          unsigned* __restrict__ myIdx, int* __restrict__ sHist,
                          int lane, int pi, int pj, int gw, int nw, int B,
                          float icpt, bool uni)
{
    const unsigned char* ib = (const unsigned char*)myIdx;
    const int fa = 4 * lane, fc = 128 + 4 * lane;
    for (int row = gw; row < B; row += nw) {
        const float4* rp = (const float4*)(x + (size_t)row * F_DIM);
        float4 a = rp[lane], c = rp[32 + lane];
        float vv[8] = {a.x, a.y, a.z, a.w, c.x, c.y, c.z, c.w};
        int id[8];
#pragma unroll
        for (int j = 0; j < 8; ++j) {
            int f = (j < 4) ? fa + j : fc + (j - 4);
            id[j] = uni ? bin_uni(vv[j]) : bin_gen(vv[j], bins + f * 33);
        }
        float s = 0.f;
#pragma unroll
        for (int j = 0; j < 8; ++j) {
            int f = (j < 4) ? fa + j : fc + (j - 4);
            s += sW[f * 33 + id[j]];
        }
        myIdx[lane]      = (unsigned)id[0] | ((unsigned)id[1] << 8)
                         | ((unsigned)id[2] << 16) | ((unsigned)id[3] << 24);
        myIdx[32 + lane] = (unsigned)id[4] | ((unsigned)id[5] << 8)
                         | ((unsigned)id[6] << 16) | ((unsigned)id[7] << 24);
        __syncwarp();
        if (lane < P_DIM) s += sIW[lane * 1024 + ib[pi] * 32 + ib[pj]];
        if (lane == 0)      atomicAdd(&sHist[id[0]], 1);
        else if (lane == 1) atomicAdd(&sHist[32 + id[1]], 1);
#pragma unroll
        for (int off = 16; off > 0; off >>= 1)
            s += __shfl_xor_sync(0xffffffffu, s, off);
        if (lane == 0) out[row] = icpt + s;
    }
}

__global__ __launch_bounds__(THREADS, 1)
void fair_ebm_kernel(const float* __restrict__ x, const float* __restrict__ W,
                     const float* __restrict__ IW, const float* __restrict__ intercept,
                     const float* __restrict__ bins, const int* __restrict__ pair_i,
                     const int* __restrict__ pair_j, float* __restrict__ out,
                     int B, int writeLoss)
{
    extern __shared__ float smem[];
    float*    sW    = smem;                                   // 256*33 floats
    float*    sIW   = sW + F_DIM * 33;                        // 32*1024 floats
    unsigned* sIdx  = (unsigned*)(sIW + P_DIM * NB * NB);     // NWARPS*64
    int*      sHist = (int*)(sIdx + NWARPS * 64);             // 64
    int*      sFlag = sHist + 64;                             // 2

    const int tid = threadIdx.x;
    if (tid == 0) { sFlag[0] = 1; sFlag[1] = 1; }
    if (tid < 64) sHist[tid] = 0;
    __syncthreads();

    // ---- stage W (bank-padded) and IW; verify bins + pairs from gmem ----
    {
        const float4* W4 = (const float4*)W;
        for (int i = tid; i < (F_DIM * NB) / 4; i += THREADS) {
            float4 v = W4[i];
            int e = i * 4;
            float* d = sW + (e >> 5) * 33 + (e & 31);   // (e&31)<=28, no wrap
            d[0] = v.x; d[1] = v.y; d[2] = v.z; d[3] = v.w;
        }
    }
    {
        const float4* IW4 = (const float4*)IW;
        float4* sIW4 = (float4*)sIW;
        for (int i = tid; i < (P_DIM * NB * NB) / 4; i += THREADS) sIW4[i] = IW4[i];
    }
    {
        const float4* B4 = (const float4*)bins;
        bool bad = false;
        for (int i = tid; i < (F_DIM * 33) / 4; i += THREADS) {
            float4 v = B4[i];
            int e = i * 4;
            bad |= (v.x != (float)((e + 0) % 33) * 0.03125f);
            bad |= (v.y != (float)((e + 1) % 33) * 0.03125f);
            bad |= (v.z != (float)((e + 2) % 33) * 0.03125f);
            bad |= (v.w != (float)((e + 3) % 33) * 0.03125f);
        }
        if (bad) sFlag[0] = 0;
    }
    if (tid < P_DIM) {
        if (pair_i[tid] != 2 * tid || pair_j[tid] != 2 * tid + 1) sFlag[1] = 0;
    }
    __syncthreads();

    const bool  uni   = (sFlag[0] != 0);
    const bool  pfast = (sFlag[1] != 0);
    const float icpt  = intercept[0];
    const int   lane  = tid & 31;
    const int   warp  = tid >> 5;
    const int   gw    = blockIdx.x * NWARPS + warp;
    const int   nw    = gridDim.x * NWARPS;

    if (uni && pfast) {
        fast_loop(x, out, sW, sIW, sHist, lane, gw, nw, B, icpt);
    } else {
        int mpi = pair_i[lane & (P_DIM - 1)];
        int mpj = pair_j[lane & (P_DIM - 1)];
        slow_loop(x, out, sW, sIW, bins, sIdx + warp * 64, sHist,
                  lane, mpi, mpj, gw, nw, B, icpt, uni);
    }

    // ---- cross-block reduce + last-block finalize ----
    __syncthreads();
    if (tid < 64) atomicAdd(&g_hist[tid], sHist[tid]);
    __threadfence();
    __syncthreads();

    __shared__ unsigned ticket;
    if (tid == 0) ticket = atomicAdd(&g_ctr, 1u);
    __syncthreads();

    if (ticket == gridDim.x - 1) {
        if (tid < 64) sHist[tid] = atomicAdd(&g_hist[tid], 0);
        __syncthreads();
        if (tid < 32) {
            const double invB = 1.0 / (double)B;
            double vsum = 0.0;
#pragma unroll
            for (int s2i = 0; s2i < 2; ++s2i) {
                const int f = s2i ? 5 : 0;
                double w   = (double)W[f * NB + tid];
                double cnt = (double)sHist[s2i * 32 + tid];
                double t1 = cnt * w;
                double t2 = t1 * w;
#pragma unroll
                for (int off = 16; off > 0; off >>= 1) {
                    t1 += __shfl_xor_sync(0xffffffffu, t1, off);
                    t2 += __shfl_xor_sync(0xffffffffu, t2, off);
                }
                double mean = t1 * invB;
                vsum += t2 * invB - mean * mean;
            }
            if (tid == 0) {
                if (writeLoss) out[B] = (float)(0.1 * vsum);
                g_ctr = 0;
            }
        }
        if (tid < 64) g_hist[tid] = 0;
        __threadfence();
    }
}

extern "C" void kernel_launch(void* const* d_in, const int* in_sizes, int n_in,
                              void* d_out, int out_size)
{
    const float* x         = (const float*)d_in[0];
    const float* W         = (const float*)d_in[1];
    const float* IW        = (const float*)d_in[2];
    const float* intercept = (const float*)d_in[3];
    const float* bins      = (const float*)d_in[4];
    const int*   pair_i    = (const int*)d_in[5];
    const int*   pair_j    = (const int*)d_in[6];
    float*       out       = (float*)d_out;

    const int B = in_sizes[0] / F_DIM;
    const int writeLoss = (out_size > B) ? 1 : 0;

    int dev = 0;
    cudaGetDevice(&dev);
    int sms = 148;
    cudaDeviceGetAttribute(&sms, cudaDevAttrMultiProcessorCount, dev);

    const size_t shbytes =
        (size_t)(F_DIM * 33 + P_DIM * NB * NB + NWARPS * 64) * 4 + 64 * 4 + 16;
    cudaFuncSetAttribute(fair_ebm_kernel,
                         cudaFuncAttributeMaxDynamicSharedMemorySize, (int)shbytes);

    fair_ebm_kernel<<<sms, THREADS, shbytes>>>(x, W, IW, intercept, bins,
                                               pair_i, pair_j, out, B, writeLoss);
}

// round 9
// speedup vs baseline: 1.3919x; 1.3919x over previous
#include <cuda_runtime.h>

#define F_DIM 256
#define NB 32
#define P_DIM 32
#define THREADS 896
#define NWARPS (THREADS / 32)

// Cross-launch accumulators: zero at process start; the LAST block of every
// launch resets them after consuming, so graph replays are deterministic.
__device__ int g_hist[64];
__device__ unsigned int g_ctr = 0;

// bins verified on-device to be exactly k/32 (exact power-of-two scale in
// fp32, so floor(x*32) clipped == count(x >= k/32) - 1 clipped).
__device__ __forceinline__ int bin_uni(float v) {
    int k = (int)(v * 32.0f);
    k = k < 0 ? 0 : k;
    return k > 31 ? 31 : k;
}
__device__ __forceinline__ int bin_gen(float v, const float* __restrict__ e) {
    int c = 0;
#pragma unroll
    for (int k = 0; k < 33; ++k) c += (v >= e[k]) ? 1 : 0;
    c -= 1;
    c = c < 0 ? 0 : c;
    return c > 31 ? 31 : c;
}

// Warp sum via butterfly (sm_103 has no f32 redux). Result on all lanes.
__device__ __forceinline__ float warp_sum(float v) {
#pragma unroll
    for (int off = 16; off > 0; off >>= 1)
        v += __shfl_xor_sync(0xffffffffu, v, off);
    return v;
}

// ---------------- fast path ----------------
// Warp owns contiguous row pair (2pr, 2pr+1): 4 LDG.128 over 2KB contiguous.
// Lanes 0-15 compute pairs (2l, 2l+1) locally from their own float4 (no
// exchange); their low-feature W contribution is folded into sIW2.
__device__ void fast_loop(const float4* __restrict__ xp, float* __restrict__ out,
                          const float* __restrict__ sW, const float* __restrict__ sIW2,
                          int* __restrict__ sHist,
                          int lane, int pr, int nw, int B, float icpt,
                          float4 v0, float4 v1, float4 v2, float4 v3)
{
    const unsigned full = 0xffffffffu;
    int h0 = 0, h5 = 0;
    const int fa = 4 * lane;
    const int fc = 128 + 4 * lane;

    if (2 * pr < B) {
        while (true) {
            // ---- prefetch next pair (clamped, branchless) ----
            const int prn = pr + nw;
            const bool morep = (2 * prn) < B;
            const int pc = morep ? prn : pr;
            int rB = 2 * pc + 1; rB = rB < B ? rB : (B - 1);
            const size_t b0 = (size_t)(2 * pc) * 64;
            const size_t b1 = (size_t)rB * 64;
            float4 n0 = xp[b0 + lane];
            float4 n1 = xp[b0 + 32 + lane];
            float4 n2 = xp[b1 + lane];
            float4 n3 = xp[b1 + 32 + lane];

            // ---- bins (register math only) ----
            int p0 = bin_uni(v0.x), p1 = bin_uni(v0.y), p2 = bin_uni(v0.z), p3 = bin_uni(v0.w);
            int p4 = bin_uni(v1.x), p5 = bin_uni(v1.y), p6 = bin_uni(v1.z), p7 = bin_uni(v1.w);
            int q0 = bin_uni(v2.x), q1 = bin_uni(v2.y), q2 = bin_uni(v2.z), q3 = bin_uni(v2.w);
            int q4 = bin_uni(v3.x), q5 = bin_uni(v3.y), q6 = bin_uni(v3.z), q7 = bin_uni(v3.w);

            // ---- high-feature W gathers (all lanes) ----
            float s0 = sW[(fc + 0) * 33 + p4] + sW[(fc + 1) * 33 + p5]
                     + sW[(fc + 2) * 33 + p6] + sW[(fc + 3) * 33 + p7];
            float s1 = sW[(fc + 0) * 33 + q4] + sW[(fc + 1) * 33 + q5]
                     + sW[(fc + 2) * 33 + q6] + sW[(fc + 3) * 33 + q7];

            if (lane >= 16) {
                // features 64..127: plain W gathers (half-warp active)
                s0 += sW[(fa + 0) * 33 + p0] + sW[(fa + 1) * 33 + p1]
                    + sW[(fa + 2) * 33 + p2] + sW[(fa + 3) * 33 + p3];
                s1 += sW[(fa + 0) * 33 + q0] + sW[(fa + 1) * 33 + q1]
                    + sW[(fa + 2) * 33 + q2] + sW[(fa + 3) * 33 + q3];
            } else {
                // features 4l..4l+3 = pairs 2l,2l+1; W folded into sIW2
                const float* t0 = sIW2 + (2 * lane) * 1024;
                const float* t1 = sIW2 + (2 * lane + 1) * 1024;
                s0 += t0[p0 * 32 + p1] + t1[p2 * 32 + p3];
                s1 += t0[q0 * 32 + q1] + t1[q2 * 32 + q3];
            }

            // ---- sensitive histograms (feature 0 = lane0.x, 5 = lane1.y) ----
            const bool rv1 = (2 * pr + 1) < B;
            int b0a = __shfl_sync(full, p0, 0);
            int b5a = __shfl_sync(full, p1, 1);
            int b0b = __shfl_sync(full, q0, 0);
            int b5b = __shfl_sync(full, q1, 1);
            h0 += (lane == b0a) + ((rv1 && lane == b0b) ? 1 : 0);
            h5 += (lane == b5a) + ((rv1 && lane == b5b) ? 1 : 0);

            // ---- dual interleaved butterfly (chains pipeline) ----
#pragma unroll
            for (int off = 16; off > 0; off >>= 1) {
                s0 += __shfl_xor_sync(full, s0, off);
                s1 += __shfl_xor_sync(full, s1, off);
            }
            if (lane == 0) {
                int r0 = 2 * pr;
                if (rv1) {
                    float2 o; o.x = icpt + s0; o.y = icpt + s1;
                    *(float2*)(out + r0) = o;
                } else {
                    out[r0] = icpt + s0;
                }
            }

            if (!morep) break;
            pr = prn;
            v0 = n0; v1 = n1; v2 = n2; v3 = n3;
        }
    }
    atomicAdd(&sHist[lane], h0);
    atomicAdd(&sHist[32 + lane], h5);
}

// ---------------- generic fallback (correctness only) ----------------
__device__ void slow_loop(const float* __restrict__ x, float* __restrict__ out,
                          const float* __restrict__ sW, const float* __restrict__ sIW,
                          const float* __restrict__ bins,
                          unsigned* __restrict__ myIdx, int* __restrict__ sHist,
                          int lane, int pi, int pj, int gw, int nw, int B,
                          float icpt, bool uni)
{
    const unsigned char* ib = (const unsigned char*)myIdx;
    const int fa = 4 * lane, fc = 128 + 4 * lane;
    for (int row = gw; row < B; row += nw) {
        const float4* rp = (const float4*)(x + (size_t)row * F_DIM);
        float4 a = rp[lane], c = rp[32 + lane];
        float vv[8] = {a.x, a.y, a.z, a.w, c.x, c.y, c.z, c.w};
        int id[8];
#pragma unroll
        for (int j = 0; j < 8; ++j) {
            int f = (j < 4) ? fa + j : fc + (j - 4);
            id[j] = uni ? bin_uni(vv[j]) : bin_gen(vv[j], bins + f * 33);
        }
        float s = 0.f;
#pragma unroll
        for (int j = 0; j < 8; ++j) {
            int f = (j < 4) ? fa + j : fc + (j - 4);
            s += sW[f * 33 + id[j]];
        }
        myIdx[lane]      = (unsigned)id[0] | ((unsigned)id[1] << 8)
                         | ((unsigned)id[2] << 16) | ((unsigned)id[3] << 24);
        myIdx[32 + lane] = (unsigned)id[4] | ((unsigned)id[5] << 8)
                         | ((unsigned)id[6] << 16) | ((unsigned)id[7] << 24);
        __syncwarp();
        if (lane < P_DIM) s += sIW[lane * 1024 + ib[pi] * 32 + ib[pj]];
        if (lane == 0)      atomicAdd(&sHist[id[0]], 1);
        else if (lane == 1) atomicAdd(&sHist[32 + id[1]], 1);
        s = warp_sum(s);
        if (lane == 0) out[row] = icpt + s;
    }
}

__global__ __launch_bounds__(THREADS, 1)
void fair_ebm_kernel(const float* __restrict__ x, const float* __restrict__ W,
                     const float* __restrict__ IW, const float* __restrict__ intercept,
                     const float* __restrict__ bins, const int* __restrict__ pair_i,
                     const int* __restrict__ pair_j, float* __restrict__ out,
                     int B, int writeLoss)
{
    extern __shared__ float smem[];
    float*    sW    = smem;                                   // 256*33
    float*    sIW   = sW + F_DIM * 33;                        // 32*1024 (folded on fast path)
    unsigned* sIdx  = (unsigned*)(sIW + P_DIM * NB * NB);     // NWARPS*64
    int*      sHist = (int*)(sIdx + NWARPS * 64);             // 64
    int*      sFlag = sHist + 64;                             // 2

    const int tid  = threadIdx.x;
    const int lane = tid & 31;
    const int warp = tid >> 5;
    const int gw   = blockIdx.x * NWARPS + warp;
    const int nw   = gridDim.x * NWARPS;

    // ---- issue first x tile NOW so DRAM ramps during staging ----
    const float4* xp = (const float4*)x;
    float4 v0, v1, v2, v3;
    {
        int pc = (2 * gw < B) ? gw : 0;
        int rB = 2 * pc + 1; rB = rB < B ? rB : (B - 1);
        size_t b0 = (size_t)(2 * pc) * 64, b1 = (size_t)rB * 64;
        v0 = xp[b0 + lane]; v1 = xp[b0 + 32 + lane];
        v2 = xp[b1 + lane]; v3 = xp[b1 + 32 + lane];
    }

    if (tid == 0) { sFlag[0] = 1; sFlag[1] = 1; }
    if (tid < 64) sHist[tid] = 0;

    // ---- stage W (bank-padded, stride 33) ----
    {
        const float4* W4 = (const float4*)W;
        for (int i = tid; i < (F_DIM * NB) / 4; i += THREADS) {
            float4 v = W4[i];
            int e = i * 4;
            float* d = sW + (e >> 5) * 33 + (e & 31);   // (e&31) <= 28, no wrap
            d[0] = v.x; d[1] = v.y; d[2] = v.z; d[3] = v.w;
        }
    }
    // ---- verify uniform bins + identity pairs ----
    {
        const float4* B4 = (const float4*)bins;
        bool bad = false;
        for (int i = tid; i < (F_DIM * 33) / 4; i += THREADS) {
            float4 v = B4[i];
            int e = i * 4;
            bad |= (v.x != (float)((e + 0) % 33) * 0.03125f);
            bad |= (v.y != (float)((e + 1) % 33) * 0.03125f);
            bad |= (v.z != (float)((e + 2) % 33) * 0.03125f);
            bad |= (v.w != (float)((e + 3) % 33) * 0.03125f);
        }
        if (bad) sFlag[0] = 0;
    }
    if (tid < P_DIM) {
        if (pair_i[tid] != 2 * tid || pair_j[tid] != 2 * tid + 1) sFlag[1] = 0;
    }
    __syncthreads();

    const bool fast = (sFlag[0] != 0) && (sFlag[1] != 0);

    // ---- stage IW: folded (IW + main effects of features 0..63) if fast ----
    {
        const float4* IW4 = (const float4*)IW;
        float4* sIW4 = (float4*)sIW;
        if (fast) {
            for (int i = tid; i < (P_DIM * NB * NB) / 4; i += THREADS) {
                float4 v = IW4[i];
                int e = i * 4;
                int p = e >> 10;
                int a = (e >> 5) & 31;
                int bb = e & 31;                          // multiple of 4
                float wa = sW[(2 * p) * 33 + a];
                const float* wb = sW + (2 * p + 1) * 33 + bb;
                v.x += wa + wb[0]; v.y += wa + wb[1];
                v.z += wa + wb[2]; v.w += wa + wb[3];
                sIW4[i] = v;
            }
        } else {
            for (int i = tid; i < (P_DIM * NB * NB) / 4; i += THREADS)
                sIW4[i] = IW4[i];
        }
    }
    __syncthreads();

    const float icpt = intercept[0];

    if (fast) {
        fast_loop(xp, out, sW, sIW, sHist, lane, gw, nw, B, icpt, v0, v1, v2, v3);
    } else {
        int mpi = pair_i[lane & (P_DIM - 1)];
        int mpj = pair_j[lane & (P_DIM - 1)];
        slow_loop(x, out, sW, sIW, bins, sIdx + warp * 64, sHist,
                  lane, mpi, mpj, gw, nw, B, icpt, sFlag[0] != 0);
    }

    // ---- cross-block reduce + last-block finalize ----
    __syncthreads();
    if (tid < 64) atomicAdd(&g_hist[tid], sHist[tid]);
    __threadfence();
    __syncthreads();

    __shared__ unsigned ticket;
    if (tid == 0) ticket = atomicAdd(&g_ctr, 1u);
    __syncthreads();

    if (ticket == gridDim.x - 1) {
        if (tid < 64) sHist[tid] = atomicAdd(&g_hist[tid], 0);
        __syncthreads();
        if (tid < 32) {
            const double invB = 1.0 / (double)B;
            double vsum = 0.0;
#pragma unroll
            for (int s2i = 0; s2i < 2; ++s2i) {
                const int f = s2i ? 5 : 0;
                double w   = (double)W[f * NB + tid];
                double cnt = (double)sHist[s2i * 32 + tid];
                double t1 = cnt * w;
                double t2 = t1 * w;
#pragma unroll
                for (int off = 16; off > 0; off >>= 1) {
                    t1 += __shfl_xor_sync(0xffffffffu, t1, off);
                    t2 += __shfl_xor_sync(0xffffffffu, t2, off);
                }
                double mean = t1 * invB;
                vsum += t2 * invB - mean * mean;
            }
            if (tid == 0) {
                if (writeLoss) out[B] = (float)(0.1 * vsum);
                g_ctr = 0;
            }
        }
        if (tid < 64) g_hist[tid] = 0;
        __threadfence();
    }
}

extern "C" void kernel_launch(void* const* d_in, const int* in_sizes, int n_in,
                              void* d_out, int out_size)
{
    const float* x         = (const float*)d_in[0];
    const float* W         = (const float*)d_in[1];
    const float* IW        = (const float*)d_in[2];
    const float* intercept = (const float*)d_in[3];
    const float* bins      = (const float*)d_in[4];
    const int*   pair_i    = (const int*)d_in[5];
    const int*   pair_j    = (const int*)d_in[6];
    float*       out       = (float*)d_out;

    const int B = in_sizes[0] / F_DIM;
    const int writeLoss = (out_size > B) ? 1 : 0;

    int dev = 0;
    cudaGetDevice(&dev);
    int sms = 148;
    cudaDeviceGetAttribute(&sms, cudaDevAttrMultiProcessorCount, dev);

    const size_t shbytes =
        (size_t)(F_DIM * 33 + P_DIM * NB * NB + NWARPS * 64) * 4 + 64 * 4 + 16;
    cudaFuncSetAttribute(fair_ebm_kernel,
                         cudaFuncAttributeMaxDynamicSharedMemorySize, (int)shbytes);

    fair_ebm_kernel<<<sms, THREADS, shbytes>>>(x, W, IW, intercept, bins,
                                               pair_i, pair_j, out, B, writeLoss);
}

// round 10
// speedup vs baseline: 1.5292x; 1.0986x over previous
#include <cuda_runtime.h>

#define NB 32
#define THREADS 896
#define NWARPS 28
#define MAXB 16          // rows per warp batch (= RPW for B=65536, grid=152)

// Cross-launch accumulators: zero at process start; the LAST block of every
// launch resets them after consuming, so graph replays are deterministic.
__device__ int g_hist[64];
__device__ unsigned int g_ctr = 0;

// Exact floor(clip(v)*32) without cvt pipe: saturate, FFMA.RZ with 2^23
// (truncation == floor for non-negative), extract low bits. NaN -> 0, which
// matches the reference (all comparisons false -> -1 -> clip 0).
__device__ __forceinline__ int bin_uni(float v) {
    float t = __saturatef(v);
    float y = __fmaf_rz(t, 32.0f, 8388608.0f);   // 2^23
    int k = __float_as_int(y) & 63;              // 0..32
    return k > 31 ? 31 : k;
}
__device__ __forceinline__ int bin_gen(float v, const float* __restrict__ e) {
    int c = 0;
#pragma unroll
    for (int k = 0; k < 33; ++k) c += (v >= e[k]) ? 1 : 0;
    c -= 1;
    c = c < 0 ? 0 : c;
    return c > 31 ? 31 : c;
}

__device__ __forceinline__ float warp_sum(float v) {
#pragma unroll
    for (int off = 16; off > 0; off >>= 1)
        v += __shfl_xor_sync(0xffffffffu, v, off);
    return v;
}

// ---------------- generic fallback (correctness only, pure gmem) ----------------
__device__ void slow_loop(const float* __restrict__ x, float* __restrict__ out,
                          const float* __restrict__ W, const float* __restrict__ IW,
                          const float* __restrict__ bins,
                          const int* __restrict__ pair_i, const int* __restrict__ pair_j,
                          unsigned* __restrict__ myIdx, int* __restrict__ sHist,
                          int lane, int P, int gw, int nw, int B, float icpt, bool uni)
{
    const unsigned char* ib = (const unsigned char*)myIdx;
    const int fa = 4 * lane, fc = 128 + 4 * lane;
    int mpi = (lane < P) ? pair_i[lane] : 0;
    int mpj = (lane < P) ? pair_j[lane] : 0;
    for (int row = gw; row < B; row += nw) {
        const float4* rp = (const float4*)(x + (size_t)row * 256);
        float4 a = rp[lane], c = rp[32 + lane];
        float vv[8] = {a.x, a.y, a.z, a.w, c.x, c.y, c.z, c.w};
        int id[8];
#pragma unroll
        for (int j = 0; j < 8; ++j) {
            int f = (j < 4) ? fa + j : fc + (j - 4);
            id[j] = uni ? bin_uni(vv[j]) : bin_gen(vv[j], bins + f * 33);
        }
        float s = 0.f;
#pragma unroll
        for (int j = 0; j < 8; ++j) {
            int f = (j < 4) ? fa + j : fc + (j - 4);
            s += __ldg(&W[f * 32 + id[j]]);
        }
        myIdx[lane]      = (unsigned)id[0] | ((unsigned)id[1] << 8)
                         | ((unsigned)id[2] << 16) | ((unsigned)id[3] << 24);
        myIdx[32 + lane] = (unsigned)id[4] | ((unsigned)id[5] << 8)
                         | ((unsigned)id[6] << 16) | ((unsigned)id[7] << 24);
        __syncwarp();
        if (lane < P) s += __ldg(&IW[lane * 1024 + ib[mpi] * 32 + ib[mpj]]);
        if (lane == 0)      atomicAdd(&sHist[id[0]], 1);
        else if (lane == 1) atomicAdd(&sHist[32 + id[1]], 1);
        s = warp_sum(s);
        if (lane == 0) out[row] = icpt + s;
    }
}

__global__ __launch_bounds__(THREADS, 1)
void fair_ebm_kernel(const float* __restrict__ x, const float* __restrict__ W,
                     const float* __restrict__ IW, const float* __restrict__ intercept,
                     const float* __restrict__ bins, const int* __restrict__ pair_i,
                     const int* __restrict__ pair_j, float* __restrict__ out,
                     int B, int P, int writeLoss)
{
    extern __shared__ float smem[];
    float* sIW2  = smem;                     // 32*1024 folded: IW + W[2p][a] + W[2p+1][b]
    float* sWh   = sIW2 + 32768;             // W rows 64..255, stride 33 (192*33 = 6336)
    float* zeros = sWh + 6336;               // 32 zero floats (dummy-lookup target)
    float* sPart = zeros + 32;               // per-warp partials: NWARPS * MAXB * 36
    int*   sHist = (int*)(sPart + NWARPS * MAXB * 36);   // 64
    int*   sFlag = sHist + 64;                            // 2

    const int tid  = threadIdx.x;
    const int lane = tid & 31;
    const int warp = tid >> 5;
    const int TW   = gridDim.x * NWARPS;
    const int RPW  = (B + TW - 1) / TW;
    const int w    = blockIdx.x * NWARPS + warp;

    // ---- early first-tile load: ramp DRAM during staging ----
    const float4* xp4 = (const float4*)x;
    size_t er0 = (size_t)w * RPW;
    if (er0 >= (size_t)B) er0 = 0;
    float4 a0 = xp4[er0 * 64 + lane];
    float4 c0 = xp4[er0 * 64 + 32 + lane];

    if (tid == 0) { sFlag[0] = 1; sFlag[1] = 1; }
    if (tid < 64) sHist[tid] = 0;
    if (tid < 32) zeros[tid] = 0.0f;

    // ---- stage W rows 64..255 (bank-padded stride 33) ----
    {
        const float4* W4 = (const float4*)W;
        for (int i = tid; i < 1536; i += THREADS) {       // 192*32/4
            float4 v = W4[512 + i];                        // skip rows 0..63
            int f = i * 4;
            float* d = sWh + (f >> 5) * 33 + (f & 31);     // (f&31) <= 28
            d[0] = v.x; d[1] = v.y; d[2] = v.z; d[3] = v.w;
        }
    }
    // ---- verify uniform bins + identity pairs (P must be 32) ----
    {
        const float4* B4 = (const float4*)bins;
        bool bad = false;
        for (int i = tid; i < (256 * 33) / 4; i += THREADS) {
            float4 v = B4[i];
            int e = i * 4;
            bad |= (v.x != (float)((e + 0) % 33) * 0.03125f);
            bad |= (v.y != (float)((e + 1) % 33) * 0.03125f);
            bad |= (v.z != (float)((e + 2) % 33) * 0.03125f);
            bad |= (v.w != (float)((e + 3) % 33) * 0.03125f);
        }
        if (bad) sFlag[0] = 0;
    }
    if (tid == 0 && P != 32) sFlag[1] = 0;
    if (tid < 32 && tid < P) {
        if (pair_i[tid] != 2 * tid || pair_j[tid] != 2 * tid + 1) sFlag[1] = 0;
    }
    __syncthreads();

    const bool fast = (sFlag[0] != 0) && (sFlag[1] != 0);

    if (fast) {
        // fold: sIW2[p][a][b] = IW[p][a][b] + W[2p][a] + W[2p+1][b]
        const float4* IW4 = (const float4*)IW;
        float4* D4 = (float4*)sIW2;
        for (int i = tid; i < 8192; i += THREADS) {
            float4 v = IW4[i];
            int e = i * 4;
            int p = e >> 10, a = (e >> 5) & 31, b = e & 31;   // b multiple of 4
            float wa = __ldg(&W[(2 * p) * 32 + a]);
            float4 wb = __ldg((const float4*)&W[(2 * p + 1) * 32 + b]);
            v.x += wa + wb.x; v.y += wa + wb.y;
            v.z += wa + wb.z; v.w += wa + wb.w;
            D4[i] = v;
        }
    }
    __syncthreads();

    const float icpt = intercept[0];

    if (fast) {
        // per-lane loop-invariant lookup config (uniform inner loop, no branches)
        const float *ub0, *ub1, *ub2, *ub3;
        int um, vm;
        if (lane < 16) {
            ub0 = sIW2 + (2 * lane) * 1024;       // T(2l)[a][b]
            ub1 = sIW2 + (2 * lane + 1) * 1024;   // T(2l+1)[a][b]
            ub2 = zeros; ub3 = zeros;             // dummy slots
            um = 32; vm = 1;
        } else {
            int fr = 4 * lane - 64;               // sWh row of feature 4*lane
            ub0 = sWh + fr * 33;
            ub1 = sWh + (fr + 2) * 33;
            ub2 = sWh + (fr + 1) * 33;
            ub3 = sWh + (fr + 3) * 33;
            um = 1; vm = 0;
        }
        const float* hb = sWh + (64 + 4 * lane) * 33;   // feature 128+4*lane
        float* pbuf = sPart + warp * (MAXB * 36);

        size_t row0 = (size_t)w * RPW;
        int nr_total = 0;
        if (row0 < (size_t)B) {
            int rem = B - (int)row0;
            nr_total = rem < RPW ? rem : RPW;
        }

        for (int bb = 0; bb < nr_total; bb += MAXB) {
            const int nr = (nr_total - bb) < MAXB ? (nr_total - bb) : MAXB;
            const float4* xp = xp4 + (row0 + bb) * 64;
            float4 a, c;
            if (bb == 0) { a = a0; c = c0; }
            else         { a = xp[lane]; c = xp[32 + lane]; }

            for (int r = 0; r < nr; ++r) {
                // prefetch next row (clamped)
                int rn = (r + 1 < nr) ? (r + 1) : r;
                const float4* xn = xp + rn * 64;
                float4 na = xn[lane];
                float4 nc = xn[32 + lane];

                int p0 = bin_uni(a.x), p1 = bin_uni(a.y), p2 = bin_uni(a.z), p3 = bin_uni(a.w);
                int p4 = bin_uni(c.x), p5 = bin_uni(c.y), p6 = bin_uni(c.z), p7 = bin_uni(c.w);

                // unified low-feature lookups (folded tables or plain W)
                float s = ub0[p0 * um + p1 * vm]
                        + ub1[p2 * um + p3 * vm]
                        + ub2[p1]
                        + ub3[p3]
                // high-feature plain gathers (constant offsets fold into LDS)
                        + hb[p4] + hb[33 + p5] + hb[66 + p6] + hb[99 + p7];

                if (lane == 0)      atomicAdd(&sHist[p0], 1);
                else if (lane == 1) atomicAdd(&sHist[32 + p1], 1);

                pbuf[r * 36 + lane] = s;
                a = na; c = nc;
            }
            __syncwarp();
            // transpose flush: lane r sums the 32 partials of row r
            if (lane < nr) {
                const float4* rp = (const float4*)(pbuf + lane * 36);
                float4 t0 = rp[0], t1 = rp[1], t2 = rp[2], t3 = rp[3];
                float4 t4 = rp[4], t5 = rp[5], t6 = rp[6], t7 = rp[7];
                float s01 = (t0.x + t0.y) + (t0.z + t0.w);
                float s23 = (t1.x + t1.y) + (t1.z + t1.w);
                float s45 = (t2.x + t2.y) + (t2.z + t2.w);
                float s67 = (t3.x + t3.y) + (t3.z + t3.w);
                float s89 = (t4.x + t4.y) + (t4.z + t4.w);
                float sab = (t5.x + t5.y) + (t5.z + t5.w);
                float scd = (t6.x + t6.y) + (t6.z + t6.w);
                float sef = (t7.x + t7.y) + (t7.z + t7.w);
                float tot = ((s01 + s23) + (s45 + s67)) + ((s89 + sab) + (scd + sef));
                out[row0 + bb + lane] = icpt + tot;
            }
            __syncwarp();
        }
    } else {
        unsigned* myIdx = (unsigned*)(sPart + warp * (MAXB * 36));
        slow_loop(x, out, W, IW, bins, pair_i, pair_j, myIdx, sHist,
                  lane, P, w, TW, B, icpt, sFlag[0] != 0);
    }

    // ---- cross-block reduce + last-block finalize ----
    __syncthreads();
    if (tid < 64) atomicAdd(&g_hist[tid], sHist[tid]);
    __threadfence();
    __syncthreads();

    __shared__ unsigned ticket;
    if (tid == 0) ticket = atomicAdd(&g_ctr, 1u);
    __syncthreads();

    if (ticket == gridDim.x - 1) {
        if (tid < 64) sHist[tid] = atomicAdd(&g_hist[tid], 0);
        __syncthreads();
        if (tid < 32) {
            const double invB = 1.0 / (double)B;
            double vsum = 0.0;
#pragma unroll
            for (int s2i = 0; s2i < 2; ++s2i) {
                const int f = s2i ? 5 : 0;
                double wv  = (double)W[f * NB + tid];
                double cnt = (double)sHist[s2i * 32 + tid];
                double t1 = cnt * wv;
                double t2 = t1 * wv;
#pragma unroll
                for (int off = 16; off > 0; off >>= 1) {
                    t1 += __shfl_xor_sync(0xffffffffu, t1, off);
                    t2 += __shfl_xor_sync(0xffffffffu, t2, off);
                }
                double mean = t1 * invB;
                vsum += t2 * invB - mean * mean;
            }
            if (tid == 0) {
                if (writeLoss) out[B] = (float)(0.1 * vsum);
                g_ctr = 0;
            }
        }
        if (tid < 64) g_hist[tid] = 0;
        __threadfence();
    }
}

extern "C" void kernel_launch(void* const* d_in, const int* in_sizes, int n_in,
                              void* d_out, int out_size)
{
    const float* x         = (const float*)d_in[0];
    const float* W         = (const float*)d_in[1];
    const float* IW        = (const float*)d_in[2];
    const float* intercept = (const float*)d_in[3];
    const float* bins      = (const float*)d_in[4];
    const int*   pair_i    = (const int*)d_in[5];
    const int*   pair_j    = (const int*)d_in[6];
    float*       out       = (float*)d_out;

    const int B = in_sizes[0] / 256;
    const int P = in_sizes[2] / 1024;             // IW elements / (32*32)
    const int writeLoss = (out_size > B) ? 1 : 0;

    int dev = 0;
    cudaGetDevice(&dev);
    int sms = 148;
    cudaDeviceGetAttribute(&sms, cudaDevAttrMultiProcessorCount, dev);

    const size_t shbytes =
        (size_t)(32768 + 6336 + 32 + NWARPS * MAXB * 36) * 4 + 64 * 4 + 32;
    cudaFuncSetAttribute(fair_ebm_kernel,
                         cudaFuncAttributeMaxDynamicSharedMemorySize, (int)shbytes);

    fair_ebm_kernel<<<sms, THREADS, shbytes>>>(x, W, IW, intercept, bins,
                                               pair_i, pair_j, out, B, P, writeLoss);
}